// round 9
// baseline (speedup 1.0000x reference)
#include <cuda_runtime.h>
#include <cuda_bf16.h>
#include <math.h>

#define B_SZ 8
#define N_SZ 2048
#define F_SZ 128
#define ROWS_TOTAL (B_SZ * N_SZ)
#define ALPHA 0.2f
#define LN_EPS 1e-5f

// Scratch (__device__ globals: allocation-free rule)
__device__ float          g_h [ROWS_TOTAL * F_SZ];   // post-LN h fp32 (residual)
__device__ __nv_bfloat16  g_hb[ROWS_TOTAL * F_SZ];   // post-LN h bf16 (mma B operand)
__device__ float4         g_rc[ROWS_TOTAL];          // {exp(s1), exp(a*s1), -, -}
__device__ float2         g_e2[ROWS_TOTAL];          // {exp(s2), exp(a*s2)}
__device__ unsigned       g_adjbits[N_SZ * (N_SZ / 32)];

// ---------------------------------------------------------------------------
// Kernel 1 (1024 blocks, parity-interleaved for overlap):
//   odd  blocks: pack adj -> bitmask (32 vals/thread, int4 x8)
//   even blocks: prep (scale+GEMM+LN+score factors, h fp32+bf16)
// ---------------------------------------------------------------------------
__global__ void __launch_bounds__(256) prep_kernel(
    const float* __restrict__ x, const int* __restrict__ adj,
    const float* __restrict__ W, const float* __restrict__ a,
    const float* __restrict__ nw, const float* __restrict__ nb,
    const float* __restrict__ gamma, const float* __restrict__ beta)
{
    const int tid = threadIdx.x;
    if (blockIdx.x & 1) {                                  // ---- pack ----
        int gid = (blockIdx.x >> 1) * 256 + tid;
        const int4* src = (const int4*)adj + (size_t)gid * 8;
        unsigned bits = 0;
#pragma unroll
        for (int u = 0; u < 8; u++) {
            int4 v = src[u];
            bits |= (v.x > 0 ? 1u : 0u) << (4 * u);
            bits |= (v.y > 0 ? 1u : 0u) << (4 * u + 1);
            bits |= (v.z > 0 ? 1u : 0u) << (4 * u + 2);
            bits |= (v.w > 0 ? 1u : 0u) << (4 * u + 3);
        }
        g_adjbits[gid] = bits;
        return;
    }

    extern __shared__ float sm[];
    float* Ws  = sm;               // 16384
    float* xs  = sm + 16384;       // 4096
    float* a1s = xs + 4096;        // 128
    float* a2s = a1s + 128;        // 128
    float* gs  = a2s + 128;        // 128
    float* bs  = gs + 128;         // 128

    const int row0 = (blockIdx.x >> 1) * 32;

#pragma unroll
    for (int k = 0; k < 64; k++) Ws[k * 256 + tid] = W[k * 256 + tid];
#pragma unroll
    for (int k = 0; k < 16; k++) {
        int idx = k * 256 + tid;
        int rl = idx >> 7, f = idx & 127;
        int row = row0 + rl;
        int n = row & (N_SZ - 1);
        xs[idx] = x[(size_t)row * F_SZ + f] * (1.0f + nw[n]) + nb[n];
    }
    if (tid < 128) {
        a1s[tid] = a[tid];
        a2s[tid] = a[128 + tid];
        gs[tid]  = gamma[tid];
        bs[tid]  = beta[tid];
    }
    __syncthreads();

    const int w = tid >> 5, lane = tid & 31;
    const int rbase = w * 4;
    float acc[4][4];
#pragma unroll
    for (int r = 0; r < 4; r++)
#pragma unroll
        for (int k = 0; k < 4; k++) acc[r][k] = 0.0f;

#pragma unroll 2
    for (int f = 0; f < 128; f++) {
        float w0 = Ws[f * 128 + lane];
        float w1 = Ws[f * 128 + 32 + lane];
        float w2 = Ws[f * 128 + 64 + lane];
        float w3 = Ws[f * 128 + 96 + lane];
#pragma unroll
        for (int r = 0; r < 4; r++) {
            float xv = xs[(rbase + r) * 128 + f];
            acc[r][0] += xv * w0;
            acc[r][1] += xv * w1;
            acc[r][2] += xv * w2;
            acc[r][3] += xv * w3;
        }
    }

#pragma unroll
    for (int r = 0; r < 4; r++) {
        int row = row0 + rbase + r;
        float s = acc[r][0] + acc[r][1] + acc[r][2] + acc[r][3];
#pragma unroll
        for (int o = 16; o; o >>= 1) s += __shfl_xor_sync(0xffffffffu, s, o);
        float mu = s * 0.0078125f;
        float d0 = acc[r][0] - mu, d1 = acc[r][1] - mu;
        float d2 = acc[r][2] - mu, d3 = acc[r][3] - mu;
        float v = d0 * d0 + d1 * d1 + d2 * d2 + d3 * d3;
#pragma unroll
        for (int o = 16; o; o >>= 1) v += __shfl_xor_sync(0xffffffffu, v, o);
        float rstd = rsqrtf(v * 0.0078125f + LN_EPS);
        float h0 = d0 * rstd * gs[lane]      + bs[lane];
        float h1 = d1 * rstd * gs[32 + lane] + bs[32 + lane];
        float h2 = d2 * rstd * gs[64 + lane] + bs[64 + lane];
        float h3 = d3 * rstd * gs[96 + lane] + bs[96 + lane];
        float s1p = h0 * a1s[lane] + h1 * a1s[32 + lane] + h2 * a1s[64 + lane] + h3 * a1s[96 + lane];
        float s2p = h0 * a2s[lane] + h1 * a2s[32 + lane] + h2 * a2s[64 + lane] + h3 * a2s[96 + lane];
#pragma unroll
        for (int o = 16; o; o >>= 1) {
            s1p += __shfl_xor_sync(0xffffffffu, s1p, o);
            s2p += __shfl_xor_sync(0xffffffffu, s2p, o);
        }
        size_t ro = (size_t)row * F_SZ;
        g_h[ro + lane]      = h0;
        g_h[ro + 32 + lane] = h1;
        g_h[ro + 64 + lane] = h2;
        g_h[ro + 96 + lane] = h3;
        g_hb[ro + lane]      = __float2bfloat16(h0);
        g_hb[ro + 32 + lane] = __float2bfloat16(h1);
        g_hb[ro + 64 + lane] = __float2bfloat16(h2);
        g_hb[ro + 96 + lane] = __float2bfloat16(h3);
        if (lane == 0) {
            g_rc[row] = make_float4(__expf(s1p), __expf(ALPHA * s1p), 0.0f, 0.0f);
            g_e2[row] = make_float2(__expf(s2p), __expf(ALPHA * s2p));
        }
    }
}

// ---------------------------------------------------------------------------
// Kernel 2: attention, 512 threads, partitioned ownership, no full barriers.
// Warp (c=w&3, d=w>>2): A/i-rows = c*32..+31, B/f-cols = d*32..+31,
// pass-1 j-window = d*32..+31, stages Hs rows c-slab x cols d-slab.
// Per tile: wait own cp.async; bar(5+d) [Hs+e2]; pass1; bar(1+c) [Ps];
// stage(T+1); mma(T). p = mask ? max(E1*E2, F1*F2) : 0 (exp-free).
// SMEM: Hs[2][128][272B]=69632, Ps[2][128][272B]=69632, e2[2][1024B],
//       l_part[4][128]f32=2048 -> 143360 B.
// ---------------------------------------------------------------------------
__global__ void __launch_bounds__(512) attn_kernel(float* __restrict__ out)
{
    extern __shared__ char smc[];
    const unsigned HS_BYTES = 128 * 272;             // 34816
    const unsigned PS_OFF   = 2 * HS_BYTES;          // 69632
    const unsigned E2_OFF   = PS_OFF + 2 * HS_BYTES; // 139264
    const unsigned LP_OFF   = E2_OFF + 2048;         // 141312

    unsigned* Ps32  = (unsigned*)(smc + PS_OFF);
    float*    l_prt = (float*)(smc + LP_OFF);        // [4][128]

    const unsigned smemBase = (unsigned)__cvta_generic_to_shared(smc);
    const unsigned psBase   = smemBase + PS_OFF;

    const int tid  = threadIdx.x;
    const int w    = tid >> 5;
    const int lane = tid & 31;
    const int c    = w & 3;
    const int d    = w >> 2;
    const int a    = lane >> 2;     // 0..7
    const int bq   = lane & 3;      // 0..3
    const int b    = blockIdx.y;
    const int i0   = blockIdx.x * 128;
    const int bN   = b * N_SZ;

    const int ib2 = c * 32;
    const int fb  = d * 32;

    const __nv_bfloat16* hbb = g_hb + (size_t)bN * F_SZ;
    const float*         hbf = g_h  + (size_t)bN * F_SZ;

    // ---- per-row factors + mask pointers (rows lr[m] = ib2 + a + 8m) ----
    float E1[4], F1[4];
    const unsigned* mbase[4];
#pragma unroll
    for (int m = 0; m < 4; m++) {
        int lr = ib2 + a + 8 * m;
        float4 rc = g_rc[bN + i0 + lr];
        E1[m] = rc.x; F1[m] = rc.y;
        mbase[m] = g_adjbits + (size_t)(i0 + lr) * 64 + d;
    }

    // ---- mma ldmatrix addresses ----
    unsigned aOff[2];
#pragma unroll
    for (int ig = 0; ig < 2; ig++)
        aOff[ig] = psBase + (unsigned)(ib2 + ig * 16 + (lane & 15)) * 272
                 + (unsigned)(lane >> 4) * 16;
    const unsigned bRow  = (unsigned)(lane & 15) * 272;
    const unsigned bCol0 = (unsigned)(fb + (lane >> 4) * 8) * 2;
    const unsigned bCol1 = bCol0 + 32;

    float acc[2][4][4];
#pragma unroll
    for (int ig = 0; ig < 2; ig++)
#pragma unroll
        for (int n = 0; n < 4; n++)
#pragma unroll
            for (int r = 0; r < 4; r++) acc[ig][n][r] = 0.0f;
    float lacc[4] = {0.f, 0.f, 0.f, 0.f};

    // ---- staging: warp copies Hs rows c-slab x cols d-slab (+e2 if c==0) ----
    auto stage = [&](int T, int buf) {
        unsigned dbase = smemBase + (unsigned)buf * HS_BYTES;
#pragma unroll
        for (int m = 0; m < 4; m++) {
            int row = ib2 + a + 8 * m;
            unsigned dst = dbase + (unsigned)row * 272 + (unsigned)d * 64 + (unsigned)bq * 16;
            const void* src = hbb + (size_t)(T * 128 + row) * F_SZ + d * 32 + bq * 8;
            asm volatile("cp.async.cg.shared.global [%0], [%1], 16;" :: "r"(dst), "l"(src));
        }
        if (c == 0 && lane < 16) {
            unsigned dst = smemBase + E2_OFF + (unsigned)buf * 1024
                         + (unsigned)(d * 16 + lane) * 16;
            const void* src = g_e2 + bN + T * 128 + d * 32 + lane * 2;
            asm volatile("cp.async.cg.shared.global [%0], [%1], 16;" :: "r"(dst), "l"(src));
        }
        asm volatile("cp.async.commit_group;");
    };

    stage(0, 0);

    for (int T = 0; T < 16; T++) {
        const int buf = T & 1;

        asm volatile("cp.async.wait_group 0;");        // own stage(T)
        asm volatile("bar.sync %0, 128;" :: "r"(5 + d) : "memory");  // Hs(T) cols d + e2(T) window d

        // ---- pass 1 into Ps[buf]: rows c-slab, j-window d ----
        {
            const float4* e2p = (const float4*)(smc + E2_OFF + buf * 1024);
            unsigned mw[4];
#pragma unroll
            for (int m = 0; m < 4; m++) mw[m] = mbase[m][4 * T];
            unsigned* psb = Ps32 + buf * 8704;
#pragma unroll
            for (int pp = 0; pp < 4; pp++) {
                float4 ef = e2p[d * 16 + 4 * pp + bq];
#pragma unroll
                for (int m = 0; m < 4; m++) {
                    unsigned bits = mw[m] >> (8 * pp + 2 * bq);
                    float pa = fmaxf(E1[m] * ef.x, F1[m] * ef.y);
                    float pb = fmaxf(E1[m] * ef.z, F1[m] * ef.w);
                    pa = (bits & 1u) ? pa : 0.0f;
                    pb = (bits & 2u) ? pb : 0.0f;
                    __nv_bfloat162 qv = __floats2bfloat162_rn(pa, pb);
                    psb[(ib2 + a + 8 * m) * 68 + d * 16 + 4 * pp + bq] = *(unsigned*)&qv;
                    float2 fv = __bfloat1622float2(qv);
                    lacc[m] += fv.x + fv.y;
                }
            }
        }
        asm volatile("bar.sync %0, 128;" :: "r"(1 + c) : "memory");  // Ps c-slab ready

        if (T < 15) stage(T + 1, buf ^ 1);

        // ---- mma: ACC += P[c-slab] @ H[:, d-slab] ----
        const unsigned hsB = smemBase + (unsigned)buf * HS_BYTES;
        const unsigned psB = (unsigned)buf * HS_BYTES;
#pragma unroll
        for (int k = 0; k < 8; k++) {
            unsigned af[2][4];
#pragma unroll
            for (int ig = 0; ig < 2; ig++) {
                unsigned addr = aOff[ig] + psB + (unsigned)k * 32;
                asm volatile("ldmatrix.sync.aligned.m8n8.x4.shared.b16 {%0,%1,%2,%3}, [%4];"
                             : "=r"(af[ig][0]), "=r"(af[ig][1]), "=r"(af[ig][2]), "=r"(af[ig][3])
                             : "r"(addr));
            }
            unsigned bb[2][4];
            {
                unsigned addr = hsB + bRow + (unsigned)k * 16 * 272 + bCol0;
                asm volatile("ldmatrix.sync.aligned.m8n8.x4.trans.shared.b16 {%0,%1,%2,%3}, [%4];"
                             : "=r"(bb[0][0]), "=r"(bb[0][1]), "=r"(bb[0][2]), "=r"(bb[0][3])
                             : "r"(addr));
                addr = hsB + bRow + (unsigned)k * 16 * 272 + bCol1;
                asm volatile("ldmatrix.sync.aligned.m8n8.x4.trans.shared.b16 {%0,%1,%2,%3}, [%4];"
                             : "=r"(bb[1][0]), "=r"(bb[1][1]), "=r"(bb[1][2]), "=r"(bb[1][3])
                             : "r"(addr));
            }
#pragma unroll
            for (int ig = 0; ig < 2; ig++) {
#pragma unroll
                for (int n = 0; n < 4; n++) {
                    asm volatile(
                        "mma.sync.aligned.m16n8k16.row.col.f32.bf16.bf16.f32 "
                        "{%0,%1,%2,%3}, {%4,%5,%6,%7}, {%8,%9}, {%0,%1,%2,%3};"
                        : "+f"(acc[ig][n][0]), "+f"(acc[ig][n][1]),
                          "+f"(acc[ig][n][2]), "+f"(acc[ig][n][3])
                        : "r"(af[ig][0]), "r"(af[ig][1]), "r"(af[ig][2]), "r"(af[ig][3]),
                          "r"(bb[n >> 1][2 * (n & 1)]), "r"(bb[n >> 1][2 * (n & 1) + 1]));
                }
            }
        }
    }

    // ---- l partial sums: reduce over bq lanes, store per (d, row) ----
#pragma unroll
    for (int m = 0; m < 4; m++) {
        lacc[m] += __shfl_xor_sync(0xffffffffu, lacc[m], 1);
        lacc[m] += __shfl_xor_sync(0xffffffffu, lacc[m], 2);
        if (bq == 0) l_prt[d * 128 + ib2 + a + 8 * m] = lacc[m];
    }
    __syncthreads();

    // ---- epilogue: normalize, +residual, elu ----
#pragma unroll
    for (int ig = 0; ig < 2; ig++) {
#pragma unroll
        for (int rp = 0; rp < 2; rp++) {
            int rl = ib2 + ig * 16 + (lane >> 2) + 8 * rp;
            float lsum = l_prt[rl] + l_prt[128 + rl] + l_prt[256 + rl] + l_prt[384 + rl];
            float invl = 1.0f / lsum;
            int i = i0 + rl;
#pragma unroll
            for (int n = 0; n < 4; n++) {
                int col = fb + n * 8 + (lane & 3) * 2;
                const float2 r = *(const float2*)(hbf + (size_t)i * F_SZ + col);
                float ox = acc[ig][n][2 * rp]     * invl + r.x;
                float oy = acc[ig][n][2 * rp + 1] * invl + r.y;
                ox = ox > 0.0f ? ox : __expf(ox) - 1.0f;
                oy = oy > 0.0f ? oy : __expf(oy) - 1.0f;
                *(float2*)(out + ((size_t)bN + i) * F_SZ + col) = make_float2(ox, oy);
            }
        }
    }
}

// ---------------------------------------------------------------------------
extern "C" void kernel_launch(void* const* d_in, const int* in_sizes, int n_in,
                              void* d_out, int out_size)
{
    const float* x     = (const float*)d_in[0];
    const int*   adj   = (const int*)d_in[1];
    const float* W     = (const float*)d_in[2];
    const float* a     = (const float*)d_in[3];
    const float* nw    = (const float*)d_in[4];
    const float* nb    = (const float*)d_in[5];
    const float* gamma = (const float*)d_in[6];
    const float* beta  = (const float*)d_in[7];
    float* out = (float*)d_out;

    const int prep_smem = (16384 + 4096 + 4 * 128) * 4;       // 83968 B
    const int attn_smem = 143360;
    cudaFuncSetAttribute(prep_kernel, cudaFuncAttributeMaxDynamicSharedMemorySize, prep_smem);
    cudaFuncSetAttribute(attn_kernel, cudaFuncAttributeMaxDynamicSharedMemorySize, attn_smem);

    prep_kernel<<<1024, 256, prep_smem>>>(x, adj, W, a, nw, nb, gamma, beta);

    dim3 grid(N_SZ / 128, B_SZ);
    attn_kernel<<<grid, 512, attn_smem>>>(out);
}

// round 10
// speedup vs baseline: 1.0674x; 1.0674x over previous
#include <cuda_runtime.h>
#include <cuda_bf16.h>
#include <math.h>

#define B_SZ 8
#define N_SZ 2048
#define F_SZ 128
#define ROWS_TOTAL (B_SZ * N_SZ)
#define ALPHA 0.2f
#define LN_EPS 1e-5f

// Scratch (__device__ globals: allocation-free rule)
__device__ float          g_h [ROWS_TOTAL * F_SZ];   // post-LN h fp32 (residual)
__device__ __nv_bfloat16  g_hb[ROWS_TOTAL * F_SZ];   // post-LN h bf16 (mma B operand)
__device__ float4         g_rc[ROWS_TOTAL];          // {exp(s1), exp(a*s1), -, -}
__device__ float2         g_e2[ROWS_TOTAL];          // {exp(s2), exp(a*s2)}
__device__ unsigned       g_adjbits[N_SZ * (N_SZ / 32)];

// ---------------------------------------------------------------------------
// Kernel 1: blocks [0,512): prep (scale+GEMM+LN+score factors, h fp32+bf16).
//           blocks [512,1024): pack adj -> bitmask (32 vals/thread).
// ---------------------------------------------------------------------------
__global__ void __launch_bounds__(256) prep_kernel(
    const float* __restrict__ x, const int* __restrict__ adj,
    const float* __restrict__ W, const float* __restrict__ a,
    const float* __restrict__ nw, const float* __restrict__ nb,
    const float* __restrict__ gamma, const float* __restrict__ beta)
{
    const int tid = threadIdx.x;
    if (blockIdx.x >= 512) {                               // ---- pack ----
        int gid = (blockIdx.x - 512) * 256 + tid;
        const int4* src = (const int4*)adj + (size_t)gid * 8;
        unsigned bits = 0;
#pragma unroll
        for (int u = 0; u < 8; u++) {
            int4 v = src[u];
            bits |= (v.x > 0 ? 1u : 0u) << (4 * u);
            bits |= (v.y > 0 ? 1u : 0u) << (4 * u + 1);
            bits |= (v.z > 0 ? 1u : 0u) << (4 * u + 2);
            bits |= (v.w > 0 ? 1u : 0u) << (4 * u + 3);
        }
        g_adjbits[gid] = bits;
        return;
    }

    extern __shared__ float sm[];
    float* Ws  = sm;               // 16384
    float* xs  = sm + 16384;       // 4096
    float* a1s = xs + 4096;        // 128
    float* a2s = a1s + 128;        // 128
    float* gs  = a2s + 128;        // 128
    float* bs  = gs + 128;         // 128

    const int row0 = blockIdx.x * 32;

#pragma unroll
    for (int k = 0; k < 64; k++) Ws[k * 256 + tid] = W[k * 256 + tid];
#pragma unroll
    for (int k = 0; k < 16; k++) {
        int idx = k * 256 + tid;
        int rl = idx >> 7, f = idx & 127;
        int row = row0 + rl;
        int n = row & (N_SZ - 1);
        xs[idx] = x[(size_t)row * F_SZ + f] * (1.0f + nw[n]) + nb[n];
    }
    if (tid < 128) {
        a1s[tid] = a[tid];
        a2s[tid] = a[128 + tid];
        gs[tid]  = gamma[tid];
        bs[tid]  = beta[tid];
    }
    __syncthreads();

    const int w = tid >> 5, lane = tid & 31;
    const int rbase = w * 4;
    float acc[4][4];
#pragma unroll
    for (int r = 0; r < 4; r++)
#pragma unroll
        for (int k = 0; k < 4; k++) acc[r][k] = 0.0f;

#pragma unroll 2
    for (int f = 0; f < 128; f++) {
        float w0 = Ws[f * 128 + lane];
        float w1 = Ws[f * 128 + 32 + lane];
        float w2 = Ws[f * 128 + 64 + lane];
        float w3 = Ws[f * 128 + 96 + lane];
#pragma unroll
        for (int r = 0; r < 4; r++) {
            float xv = xs[(rbase + r) * 128 + f];
            acc[r][0] += xv * w0;
            acc[r][1] += xv * w1;
            acc[r][2] += xv * w2;
            acc[r][3] += xv * w3;
        }
    }

#pragma unroll
    for (int r = 0; r < 4; r++) {
        int row = row0 + rbase + r;
        float s = acc[r][0] + acc[r][1] + acc[r][2] + acc[r][3];
#pragma unroll
        for (int o = 16; o; o >>= 1) s += __shfl_xor_sync(0xffffffffu, s, o);
        float mu = s * 0.0078125f;
        float d0 = acc[r][0] - mu, d1 = acc[r][1] - mu;
        float d2 = acc[r][2] - mu, d3 = acc[r][3] - mu;
        float v = d0 * d0 + d1 * d1 + d2 * d2 + d3 * d3;
#pragma unroll
        for (int o = 16; o; o >>= 1) v += __shfl_xor_sync(0xffffffffu, v, o);
        float rstd = rsqrtf(v * 0.0078125f + LN_EPS);
        float h0 = d0 * rstd * gs[lane]      + bs[lane];
        float h1 = d1 * rstd * gs[32 + lane] + bs[32 + lane];
        float h2 = d2 * rstd * gs[64 + lane] + bs[64 + lane];
        float h3 = d3 * rstd * gs[96 + lane] + bs[96 + lane];
        float s1p = h0 * a1s[lane] + h1 * a1s[32 + lane] + h2 * a1s[64 + lane] + h3 * a1s[96 + lane];
        float s2p = h0 * a2s[lane] + h1 * a2s[32 + lane] + h2 * a2s[64 + lane] + h3 * a2s[96 + lane];
#pragma unroll
        for (int o = 16; o; o >>= 1) {
            s1p += __shfl_xor_sync(0xffffffffu, s1p, o);
            s2p += __shfl_xor_sync(0xffffffffu, s2p, o);
        }
        size_t ro = (size_t)row * F_SZ;
        g_h[ro + lane]      = h0;
        g_h[ro + 32 + lane] = h1;
        g_h[ro + 64 + lane] = h2;
        g_h[ro + 96 + lane] = h3;
        g_hb[ro + lane]      = __float2bfloat16(h0);
        g_hb[ro + 32 + lane] = __float2bfloat16(h1);
        g_hb[ro + 64 + lane] = __float2bfloat16(h2);
        g_hb[ro + 96 + lane] = __float2bfloat16(h3);
        if (lane == 0) {
            g_rc[row] = make_float4(__expf(s1p), __expf(ALPHA * s1p), 0.0f, 0.0f);
            g_e2[row] = make_float2(__expf(s2p), __expf(ALPHA * s2p));
        }
    }
}

// ---------------------------------------------------------------------------
// Kernel 2: attention, 512 threads. Software-pipelined: between barriers,
// pass1(T+1) (L2 loads -> FMA -> STS Ps[~buf]) and mma(T) (ldmatrix+HMMA from
// Ps[buf]/Hs[buf]) are fully independent -> high ILP. e2/masks read via __ldg
// (L2-resident, shared across CTAs) so pass1 never touches in-flight staging.
// Warp (c=w&3, d=w>>2): mma i-rows c*32..+31, f-cols d*32..+31; pass-1 rows
// c-slab x j-window d. One __syncthreads per tile.
// SMEM: Hs[2][128][272B]=69632, Ps[2][128][272B]=69632, l_part[4][128]=2048.
// ---------------------------------------------------------------------------
__global__ void __launch_bounds__(512) attn_kernel(float* __restrict__ out)
{
    extern __shared__ char smc[];
    const unsigned HS_BYTES = 128 * 272;             // 34816
    const unsigned PS_OFF   = 2 * HS_BYTES;          // 69632
    const unsigned LP_OFF   = PS_OFF + 2 * HS_BYTES; // 139264

    unsigned* Ps32  = (unsigned*)(smc + PS_OFF);
    float*    l_prt = (float*)(smc + LP_OFF);        // [4][128]

    const unsigned smemBase = (unsigned)__cvta_generic_to_shared(smc);
    const unsigned psBase   = smemBase + PS_OFF;

    const int tid  = threadIdx.x;
    const int w    = tid >> 5;
    const int lane = tid & 31;
    const int c    = w & 3;
    const int d    = w >> 2;
    const int a    = lane >> 2;     // 0..7
    const int bq   = lane & 3;      // 0..3
    const int b    = blockIdx.y;
    const int i0   = blockIdx.x * 128;
    const int bN   = b * N_SZ;

    const int ib2 = c * 32;
    const int fb  = d * 32;

    const __nv_bfloat16* hbb = g_hb + (size_t)bN * F_SZ;
    const float*         hbf = g_h  + (size_t)bN * F_SZ;
    const float2*        e2w = g_e2 + bN + d * 32 + bq * 2;   // + T*128 + pp*8

    // ---- per-row factors + mask pointers (rows lr[m] = ib2 + a + 8m) ----
    float E1[4], F1[4];
    const unsigned* mbase[4];
#pragma unroll
    for (int m = 0; m < 4; m++) {
        int lr = ib2 + a + 8 * m;
        float4 rc = g_rc[bN + i0 + lr];
        E1[m] = rc.x; F1[m] = rc.y;
        mbase[m] = g_adjbits + (size_t)(i0 + lr) * 64 + d;
    }

    // ---- mma ldmatrix addresses ----
    unsigned aOff[2];
#pragma unroll
    for (int ig = 0; ig < 2; ig++)
        aOff[ig] = psBase + (unsigned)(ib2 + ig * 16 + (lane & 15)) * 272
                 + (unsigned)(lane >> 4) * 16;
    const unsigned bRow  = (unsigned)(lane & 15) * 272;
    const unsigned bCol0 = (unsigned)(fb + (lane >> 4) * 8) * 2;
    const unsigned bCol1 = bCol0 + 32;

    float acc[2][4][4];
#pragma unroll
    for (int ig = 0; ig < 2; ig++)
#pragma unroll
        for (int n = 0; n < 4; n++)
#pragma unroll
            for (int r = 0; r < 4; r++) acc[ig][n][r] = 0.0f;
    float lacc[4] = {0.f, 0.f, 0.f, 0.f};

    // ---- staging: warp copies Hs rows c-slab x cols d-slab into Hs[buf] ----
    auto stage = [&](int T, int buf) {
        unsigned dbase = smemBase + (unsigned)buf * HS_BYTES;
#pragma unroll
        for (int m = 0; m < 4; m++) {
            int row = ib2 + a + 8 * m;
            unsigned dst = dbase + (unsigned)row * 272 + (unsigned)d * 64 + (unsigned)bq * 16;
            const void* src = hbb + (size_t)(T * 128 + row) * F_SZ + d * 32 + bq * 8;
            asm volatile("cp.async.cg.shared.global [%0], [%1], 16;" :: "r"(dst), "l"(src));
        }
        asm volatile("cp.async.commit_group;");
    };

    // ---- pass 1 for tile T into Ps[buf]: rows c-slab, j-window d, via L2 ----
    auto pass1 = [&](int T, int buf) {
        unsigned mw[4];
#pragma unroll
        for (int m = 0; m < 4; m++) mw[m] = __ldg(mbase[m] + 4 * T);
        unsigned* psb = Ps32 + buf * 8704;
#pragma unroll
        for (int pp = 0; pp < 4; pp++) {
            float4 ef = __ldg((const float4*)(e2w + T * 128 + pp * 8));  // {E2j,F2j,E2j1,F2j1}
#pragma unroll
            for (int m = 0; m < 4; m++) {
                unsigned bits = mw[m] >> (8 * pp + 2 * bq);
                float pa = fmaxf(E1[m] * ef.x, F1[m] * ef.y);
                float pb = fmaxf(E1[m] * ef.z, F1[m] * ef.w);
                pa = (bits & 1u) ? pa : 0.0f;
                pb = (bits & 2u) ? pb : 0.0f;
                __nv_bfloat162 qv = __floats2bfloat162_rn(pa, pb);
                psb[(ib2 + a + 8 * m) * 68 + d * 16 + 4 * pp + bq] = *(unsigned*)&qv;
                float2 fv = __bfloat1622float2(qv);
                lacc[m] += fv.x + fv.y;
            }
        }
    };

    // ---- prologue: tile 0 ----
    stage(0, 0);
    pass1(0, 0);
    asm volatile("cp.async.wait_group 0;");

    for (int T = 0; T < 16; T++) {
        const int buf = T & 1;
        __syncthreads();   // Ps[buf], Hs[buf] (tile T) visible to all warps

        if (T < 15) {
            stage(T + 1, buf ^ 1);     // cp.async into other Hs buffer
            pass1(T + 1, buf ^ 1);     // L2 reads + FMA + STS into other Ps buffer
        }

        // ---- mma(T): ACC += P[c-slab] @ H[:, d-slab] — independent of above ----
        const unsigned hsB = smemBase + (unsigned)buf * HS_BYTES;
        const unsigned psB = (unsigned)buf * HS_BYTES;
#pragma unroll
        for (int k = 0; k < 8; k++) {
            unsigned af[2][4];
#pragma unroll
            for (int ig = 0; ig < 2; ig++) {
                unsigned addr = aOff[ig] + psB + (unsigned)k * 32;
                asm volatile("ldmatrix.sync.aligned.m8n8.x4.shared.b16 {%0,%1,%2,%3}, [%4];"
                             : "=r"(af[ig][0]), "=r"(af[ig][1]), "=r"(af[ig][2]), "=r"(af[ig][3])
                             : "r"(addr));
            }
            unsigned bb[2][4];
            {
                unsigned addr = hsB + bRow + (unsigned)k * 16 * 272 + bCol0;
                asm volatile("ldmatrix.sync.aligned.m8n8.x4.trans.shared.b16 {%0,%1,%2,%3}, [%4];"
                             : "=r"(bb[0][0]), "=r"(bb[0][1]), "=r"(bb[0][2]), "=r"(bb[0][3])
                             : "r"(addr));
                addr = hsB + bRow + (unsigned)k * 16 * 272 + bCol1;
                asm volatile("ldmatrix.sync.aligned.m8n8.x4.trans.shared.b16 {%0,%1,%2,%3}, [%4];"
                             : "=r"(bb[1][0]), "=r"(bb[1][1]), "=r"(bb[1][2]), "=r"(bb[1][3])
                             : "r"(addr));
            }
#pragma unroll
            for (int ig = 0; ig < 2; ig++) {
#pragma unroll
                for (int n = 0; n < 4; n++) {
                    asm volatile(
                        "mma.sync.aligned.m16n8k16.row.col.f32.bf16.bf16.f32 "
                        "{%0,%1,%2,%3}, {%4,%5,%6,%7}, {%8,%9}, {%0,%1,%2,%3};"
                        : "+f"(acc[ig][n][0]), "+f"(acc[ig][n][1]),
                          "+f"(acc[ig][n][2]), "+f"(acc[ig][n][3])
                        : "r"(af[ig][0]), "r"(af[ig][1]), "r"(af[ig][2]), "r"(af[ig][3]),
                          "r"(bb[n >> 1][2 * (n & 1)]), "r"(bb[n >> 1][2 * (n & 1) + 1]));
                }
            }
        }

        asm volatile("cp.async.wait_group 0;");   // own stage(T+1) copies landed
    }

    // ---- l partial sums: reduce over bq lanes, store per (d, row) ----
#pragma unroll
    for (int m = 0; m < 4; m++) {
        lacc[m] += __shfl_xor_sync(0xffffffffu, lacc[m], 1);
        lacc[m] += __shfl_xor_sync(0xffffffffu, lacc[m], 2);
        if (bq == 0) l_prt[d * 128 + ib2 + a + 8 * m] = lacc[m];
    }
    __syncthreads();

    // ---- epilogue: normalize, +residual, elu ----
#pragma unroll
    for (int ig = 0; ig < 2; ig++) {
#pragma unroll
        for (int rp = 0; rp < 2; rp++) {
            int rl = ib2 + ig * 16 + (lane >> 2) + 8 * rp;
            float lsum = l_prt[rl] + l_prt[128 + rl] + l_prt[256 + rl] + l_prt[384 + rl];
            float invl = 1.0f / lsum;
            int i = i0 + rl;
#pragma unroll
            for (int n = 0; n < 4; n++) {
                int col = fb + n * 8 + (lane & 3) * 2;
                const float2 r = *(const float2*)(hbf + (size_t)i * F_SZ + col);
                float ox = acc[ig][n][2 * rp]     * invl + r.x;
                float oy = acc[ig][n][2 * rp + 1] * invl + r.y;
                ox = ox > 0.0f ? ox : __expf(ox) - 1.0f;
                oy = oy > 0.0f ? oy : __expf(oy) - 1.0f;
                *(float2*)(out + ((size_t)bN + i) * F_SZ + col) = make_float2(ox, oy);
            }
        }
    }
}

// ---------------------------------------------------------------------------
extern "C" void kernel_launch(void* const* d_in, const int* in_sizes, int n_in,
                              void* d_out, int out_size)
{
    const float* x     = (const float*)d_in[0];
    const int*   adj   = (const int*)d_in[1];
    const float* W     = (const float*)d_in[2];
    const float* a     = (const float*)d_in[3];
    const float* nw    = (const float*)d_in[4];
    const float* nb    = (const float*)d_in[5];
    const float* gamma = (const float*)d_in[6];
    const float* beta  = (const float*)d_in[7];
    float* out = (float*)d_out;

    const int prep_smem = (16384 + 4096 + 4 * 128) * 4;       // 83968 B
    const int attn_smem = 141312;
    cudaFuncSetAttribute(prep_kernel, cudaFuncAttributeMaxDynamicSharedMemorySize, prep_smem);
    cudaFuncSetAttribute(attn_kernel, cudaFuncAttributeMaxDynamicSharedMemorySize, attn_smem);

    prep_kernel<<<1024, 256, prep_smem>>>(x, adj, W, a, nw, nb, gamma, beta);

    dim3 grid(N_SZ / 128, B_SZ);
    attn_kernel<<<grid, 512, attn_smem>>>(out);
}

// round 11
// speedup vs baseline: 1.0694x; 1.0019x over previous
#include <cuda_runtime.h>
#include <cuda_bf16.h>
#include <math.h>

#define B_SZ 8
#define N_SZ 2048
#define F_SZ 128
#define ROWS_TOTAL (B_SZ * N_SZ)
#define ALPHA 0.2f
#define LN_EPS 1e-5f

// Scratch (__device__ globals: allocation-free rule)
__device__ float          g_h [ROWS_TOTAL * F_SZ];   // post-LN h fp32 (residual)
__device__ __nv_bfloat16  g_hb[ROWS_TOTAL * F_SZ];   // post-LN h bf16 (mma B operand)
__device__ float4         g_rc[ROWS_TOTAL];          // {exp(s1), exp(a*s1), -, -}
__device__ float2         g_e2[ROWS_TOTAL];          // {exp(s2), exp(a*s2)}
__device__ unsigned       g_adjbits[N_SZ * (N_SZ / 32)];

// ---------------------------------------------------------------------------
// Kernel 1: blocks [0,512): prep (scale+GEMM+LN+score factors, h fp32+bf16).
//           blocks [512,1024): pack adj -> bitmask (32 vals/thread).
// ---------------------------------------------------------------------------
__global__ void __launch_bounds__(256) prep_kernel(
    const float* __restrict__ x, const int* __restrict__ adj,
    const float* __restrict__ W, const float* __restrict__ a,
    const float* __restrict__ nw, const float* __restrict__ nb,
    const float* __restrict__ gamma, const float* __restrict__ beta)
{
    const int tid = threadIdx.x;
    if (blockIdx.x >= 512) {                               // ---- pack ----
        int gid = (blockIdx.x - 512) * 256 + tid;
        const int4* src = (const int4*)adj + (size_t)gid * 8;
        unsigned bits = 0;
#pragma unroll
        for (int u = 0; u < 8; u++) {
            int4 v = src[u];
            bits |= (v.x > 0 ? 1u : 0u) << (4 * u);
            bits |= (v.y > 0 ? 1u : 0u) << (4 * u + 1);
            bits |= (v.z > 0 ? 1u : 0u) << (4 * u + 2);
            bits |= (v.w > 0 ? 1u : 0u) << (4 * u + 3);
        }
        g_adjbits[gid] = bits;
        return;
    }

    extern __shared__ float sm[];
    float* Ws  = sm;               // 16384
    float* xs  = sm + 16384;       // 4096
    float* a1s = xs + 4096;        // 128
    float* a2s = a1s + 128;        // 128
    float* gs  = a2s + 128;        // 128
    float* bs  = gs + 128;         // 128

    const int row0 = blockIdx.x * 32;

#pragma unroll
    for (int k = 0; k < 64; k++) Ws[k * 256 + tid] = W[k * 256 + tid];
#pragma unroll
    for (int k = 0; k < 16; k++) {
        int idx = k * 256 + tid;
        int rl = idx >> 7, f = idx & 127;
        int row = row0 + rl;
        int n = row & (N_SZ - 1);
        xs[idx] = x[(size_t)row * F_SZ + f] * (1.0f + nw[n]) + nb[n];
    }
    if (tid < 128) {
        a1s[tid] = a[tid];
        a2s[tid] = a[128 + tid];
        gs[tid]  = gamma[tid];
        bs[tid]  = beta[tid];
    }
    __syncthreads();

    const int w = tid >> 5, lane = tid & 31;
    const int rbase = w * 4;
    float acc[4][4];
#pragma unroll
    for (int r = 0; r < 4; r++)
#pragma unroll
        for (int k = 0; k < 4; k++) acc[r][k] = 0.0f;

#pragma unroll 2
    for (int f = 0; f < 128; f++) {
        float w0 = Ws[f * 128 + lane];
        float w1 = Ws[f * 128 + 32 + lane];
        float w2 = Ws[f * 128 + 64 + lane];
        float w3 = Ws[f * 128 + 96 + lane];
#pragma unroll
        for (int r = 0; r < 4; r++) {
            float xv = xs[(rbase + r) * 128 + f];
            acc[r][0] += xv * w0;
            acc[r][1] += xv * w1;
            acc[r][2] += xv * w2;
            acc[r][3] += xv * w3;
        }
    }

#pragma unroll
    for (int r = 0; r < 4; r++) {
        int row = row0 + rbase + r;
        float s = acc[r][0] + acc[r][1] + acc[r][2] + acc[r][3];
#pragma unroll
        for (int o = 16; o; o >>= 1) s += __shfl_xor_sync(0xffffffffu, s, o);
        float mu = s * 0.0078125f;
        float d0 = acc[r][0] - mu, d1 = acc[r][1] - mu;
        float d2 = acc[r][2] - mu, d3 = acc[r][3] - mu;
        float v = d0 * d0 + d1 * d1 + d2 * d2 + d3 * d3;
#pragma unroll
        for (int o = 16; o; o >>= 1) v += __shfl_xor_sync(0xffffffffu, v, o);
        float rstd = rsqrtf(v * 0.0078125f + LN_EPS);
        float h0 = d0 * rstd * gs[lane]      + bs[lane];
        float h1 = d1 * rstd * gs[32 + lane] + bs[32 + lane];
        float h2 = d2 * rstd * gs[64 + lane] + bs[64 + lane];
        float h3 = d3 * rstd * gs[96 + lane] + bs[96 + lane];
        float s1p = h0 * a1s[lane] + h1 * a1s[32 + lane] + h2 * a1s[64 + lane] + h3 * a1s[96 + lane];
        float s2p = h0 * a2s[lane] + h1 * a2s[32 + lane] + h2 * a2s[64 + lane] + h3 * a2s[96 + lane];
#pragma unroll
        for (int o = 16; o; o >>= 1) {
            s1p += __shfl_xor_sync(0xffffffffu, s1p, o);
            s2p += __shfl_xor_sync(0xffffffffu, s2p, o);
        }
        size_t ro = (size_t)row * F_SZ;
        g_h[ro + lane]      = h0;
        g_h[ro + 32 + lane] = h1;
        g_h[ro + 64 + lane] = h2;
        g_h[ro + 96 + lane] = h3;
        g_hb[ro + lane]      = __float2bfloat16(h0);
        g_hb[ro + 32 + lane] = __float2bfloat16(h1);
        g_hb[ro + 64 + lane] = __float2bfloat16(h2);
        g_hb[ro + 96 + lane] = __float2bfloat16(h3);
        if (lane == 0) {
            g_rc[row] = make_float4(__expf(s1p), __expf(ALPHA * s1p), 0.0f, 0.0f);
            g_e2[row] = make_float2(__expf(s2p), __expf(ALPHA * s2p));
        }
    }
}

// ---------------------------------------------------------------------------
// Kernel 2: attention, 512 threads. Same structure as R10 but the mma k-loop
// is MANUALLY SOFTWARE-PIPELINED: fragments for k+1 are ldmatrix'd (into the
// alternate register set) before the HMMAs of k issue, so LDSM latency hides
// under the previous iteration's tensor ops. asm volatile preserves this
// hand-scheduled order.
// ---------------------------------------------------------------------------
__global__ void __launch_bounds__(512) attn_kernel(float* __restrict__ out)
{
    extern __shared__ char smc[];
    const unsigned HS_BYTES = 128 * 272;             // 34816
    const unsigned PS_OFF   = 2 * HS_BYTES;          // 69632
    const unsigned LP_OFF   = PS_OFF + 2 * HS_BYTES; // 139264

    unsigned* Ps32  = (unsigned*)(smc + PS_OFF);
    float*    l_prt = (float*)(smc + LP_OFF);        // [4][128]

    const unsigned smemBase = (unsigned)__cvta_generic_to_shared(smc);
    const unsigned psBase   = smemBase + PS_OFF;

    const int tid  = threadIdx.x;
    const int w    = tid >> 5;
    const int lane = tid & 31;
    const int c    = w & 3;
    const int d    = w >> 2;
    const int a    = lane >> 2;     // 0..7
    const int bq   = lane & 3;      // 0..3
    const int b    = blockIdx.y;
    const int i0   = blockIdx.x * 128;
    const int bN   = b * N_SZ;

    const int ib2 = c * 32;
    const int fb  = d * 32;

    const __nv_bfloat16* hbb = g_hb + (size_t)bN * F_SZ;
    const float*         hbf = g_h  + (size_t)bN * F_SZ;
    const float2*        e2w = g_e2 + bN + d * 32 + bq * 2;   // + T*128 + pp*8

    // ---- per-row factors + mask pointers (rows lr[m] = ib2 + a + 8m) ----
    float E1[4], F1[4];
    const unsigned* mbase[4];
#pragma unroll
    for (int m = 0; m < 4; m++) {
        int lr = ib2 + a + 8 * m;
        float4 rc = g_rc[bN + i0 + lr];
        E1[m] = rc.x; F1[m] = rc.y;
        mbase[m] = g_adjbits + (size_t)(i0 + lr) * 64 + d;
    }

    // ---- mma ldmatrix addresses ----
    unsigned aOff[2];
#pragma unroll
    for (int ig = 0; ig < 2; ig++)
        aOff[ig] = psBase + (unsigned)(ib2 + ig * 16 + (lane & 15)) * 272
                 + (unsigned)(lane >> 4) * 16;
    const unsigned bRow  = (unsigned)(lane & 15) * 272;
    const unsigned bCol0 = (unsigned)(fb + (lane >> 4) * 8) * 2;
    const unsigned bCol1 = bCol0 + 32;

    float acc[2][4][4];
#pragma unroll
    for (int ig = 0; ig < 2; ig++)
#pragma unroll
        for (int n = 0; n < 4; n++)
#pragma unroll
            for (int r = 0; r < 4; r++) acc[ig][n][r] = 0.0f;
    float lacc[4] = {0.f, 0.f, 0.f, 0.f};

    // ---- staging: warp copies Hs rows c-slab x cols d-slab into Hs[buf] ----
    auto stage = [&](int T, int buf) {
        unsigned dbase = smemBase + (unsigned)buf * HS_BYTES;
#pragma unroll
        for (int m = 0; m < 4; m++) {
            int row = ib2 + a + 8 * m;
            unsigned dst = dbase + (unsigned)row * 272 + (unsigned)d * 64 + (unsigned)bq * 16;
            const void* src = hbb + (size_t)(T * 128 + row) * F_SZ + d * 32 + bq * 8;
            asm volatile("cp.async.cg.shared.global [%0], [%1], 16;" :: "r"(dst), "l"(src));
        }
        asm volatile("cp.async.commit_group;");
    };

    // ---- pass 1 for tile T into Ps[buf]: rows c-slab, j-window d, via L2 ----
    auto pass1 = [&](int T, int buf) {
        unsigned mw[4];
#pragma unroll
        for (int m = 0; m < 4; m++) mw[m] = __ldg(mbase[m] + 4 * T);
        unsigned* psb = Ps32 + buf * 8704;
#pragma unroll
        for (int pp = 0; pp < 4; pp++) {
            float4 ef = __ldg((const float4*)(e2w + T * 128 + pp * 8));  // {E2j,F2j,E2j1,F2j1}
#pragma unroll
            for (int m = 0; m < 4; m++) {
                unsigned bits = mw[m] >> (8 * pp + 2 * bq);
                float pa = fmaxf(E1[m] * ef.x, F1[m] * ef.y);
                float pb = fmaxf(E1[m] * ef.z, F1[m] * ef.w);
                pa = (bits & 1u) ? pa : 0.0f;
                pb = (bits & 2u) ? pb : 0.0f;
                __nv_bfloat162 qv = __floats2bfloat162_rn(pa, pb);
                psb[(ib2 + a + 8 * m) * 68 + d * 16 + 4 * pp + bq] = *(unsigned*)&qv;
                float2 fv = __bfloat1622float2(qv);
                lacc[m] += fv.x + fv.y;
            }
        }
    };

    // ---- fragment load (one k-step) into caller-provided register sets ----
    auto load_frags = [&](int k, unsigned psB, unsigned hsB,
                          unsigned af[2][4], unsigned bb[2][4]) {
#pragma unroll
        for (int ig = 0; ig < 2; ig++) {
            unsigned addr = aOff[ig] + psB + (unsigned)k * 32;
            asm volatile("ldmatrix.sync.aligned.m8n8.x4.shared.b16 {%0,%1,%2,%3}, [%4];"
                         : "=r"(af[ig][0]), "=r"(af[ig][1]), "=r"(af[ig][2]), "=r"(af[ig][3])
                         : "r"(addr));
        }
        unsigned addr = hsB + bRow + (unsigned)k * 16 * 272 + bCol0;
        asm volatile("ldmatrix.sync.aligned.m8n8.x4.trans.shared.b16 {%0,%1,%2,%3}, [%4];"
                     : "=r"(bb[0][0]), "=r"(bb[0][1]), "=r"(bb[0][2]), "=r"(bb[0][3])
                     : "r"(addr));
        addr = hsB + bRow + (unsigned)k * 16 * 272 + bCol1;
        asm volatile("ldmatrix.sync.aligned.m8n8.x4.trans.shared.b16 {%0,%1,%2,%3}, [%4];"
                     : "=r"(bb[1][0]), "=r"(bb[1][1]), "=r"(bb[1][2]), "=r"(bb[1][3])
                     : "r"(addr));
    };

    auto mma_step = [&](unsigned af[2][4], unsigned bb[2][4]) {
#pragma unroll
        for (int ig = 0; ig < 2; ig++) {
#pragma unroll
            for (int n = 0; n < 4; n++) {
                asm volatile(
                    "mma.sync.aligned.m16n8k16.row.col.f32.bf16.bf16.f32 "
                    "{%0,%1,%2,%3}, {%4,%5,%6,%7}, {%8,%9}, {%0,%1,%2,%3};"
                    : "+f"(acc[ig][n][0]), "+f"(acc[ig][n][1]),
                      "+f"(acc[ig][n][2]), "+f"(acc[ig][n][3])
                    : "r"(af[ig][0]), "r"(af[ig][1]), "r"(af[ig][2]), "r"(af[ig][3]),
                      "r"(bb[n >> 1][2 * (n & 1)]), "r"(bb[n >> 1][2 * (n & 1) + 1]));
            }
        }
    };

    // ---- prologue: tile 0 ----
    stage(0, 0);
    pass1(0, 0);
    asm volatile("cp.async.wait_group 0;");

    for (int T = 0; T < 16; T++) {
        const int buf = T & 1;
        __syncthreads();   // Ps[buf], Hs[buf] (tile T) visible to all warps

        if (T < 15) {
            stage(T + 1, buf ^ 1);     // cp.async into other Hs buffer
            pass1(T + 1, buf ^ 1);     // L2 reads + FMA + STS into other Ps buffer
        }

        // ---- mma(T), software-pipelined over k ----
        const unsigned hsB = smemBase + (unsigned)buf * HS_BYTES;
        const unsigned psB = (unsigned)buf * HS_BYTES;

        unsigned afP[2][2][4], bbP[2][2][4];   // [stage][ig|pair][4]
        load_frags(0, psB, hsB, afP[0], bbP[0]);
#pragma unroll
        for (int k = 0; k < 8; k++) {
            if (k < 7) load_frags(k + 1, psB, hsB, afP[(k + 1) & 1], bbP[(k + 1) & 1]);
            mma_step(afP[k & 1], bbP[k & 1]);
        }

        asm volatile("cp.async.wait_group 0;");   // own stage(T+1) copies landed
    }

    // ---- l partial sums: reduce over bq lanes, store per (d, row) ----
#pragma unroll
    for (int m = 0; m < 4; m++) {
        lacc[m] += __shfl_xor_sync(0xffffffffu, lacc[m], 1);
        lacc[m] += __shfl_xor_sync(0xffffffffu, lacc[m], 2);
        if (bq == 0) l_prt[d * 128 + ib2 + a + 8 * m] = lacc[m];
    }
    __syncthreads();

    // ---- epilogue: normalize, +residual, elu ----
#pragma unroll
    for (int ig = 0; ig < 2; ig++) {
#pragma unroll
        for (int rp = 0; rp < 2; rp++) {
            int rl = ib2 + ig * 16 + (lane >> 2) + 8 * rp;
            float lsum = l_prt[rl] + l_prt[128 + rl] + l_prt[256 + rl] + l_prt[384 + rl];
            float invl = 1.0f / lsum;
            int i = i0 + rl;
#pragma unroll
            for (int n = 0; n < 4; n++) {
                int col = fb + n * 8 + (lane & 3) * 2;
                const float2 r = *(const float2*)(hbf + (size_t)i * F_SZ + col);
                float ox = acc[ig][n][2 * rp]     * invl + r.x;
                float oy = acc[ig][n][2 * rp + 1] * invl + r.y;
                ox = ox > 0.0f ? ox : __expf(ox) - 1.0f;
                oy = oy > 0.0f ? oy : __expf(oy) - 1.0f;
                *(float2*)(out + ((size_t)bN + i) * F_SZ + col) = make_float2(ox, oy);
            }
        }
    }
}

// ---------------------------------------------------------------------------
extern "C" void kernel_launch(void* const* d_in, const int* in_sizes, int n_in,
                              void* d_out, int out_size)
{
    const float* x     = (const float*)d_in[0];
    const int*   adj   = (const int*)d_in[1];
    const float* W     = (const float*)d_in[2];
    const float* a     = (const float*)d_in[3];
    const float* nw    = (const float*)d_in[4];
    const float* nb    = (const float*)d_in[5];
    const float* gamma = (const float*)d_in[6];
    const float* beta  = (const float*)d_in[7];
    float* out = (float*)d_out;

    const int prep_smem = (16384 + 4096 + 4 * 128) * 4;       // 83968 B
    const int attn_smem = 141312;
    cudaFuncSetAttribute(prep_kernel, cudaFuncAttributeMaxDynamicSharedMemorySize, prep_smem);
    cudaFuncSetAttribute(attn_kernel, cudaFuncAttributeMaxDynamicSharedMemorySize, attn_smem);

    prep_kernel<<<1024, 256, prep_smem>>>(x, adj, W, a, nw, nb, gamma, beta);

    dim3 grid(N_SZ / 128, B_SZ);
    attn_kernel<<<grid, 512, attn_smem>>>(out);
}

// round 12
// speedup vs baseline: 1.0855x; 1.0151x over previous
#include <cuda_runtime.h>
#include <cuda_bf16.h>
#include <math.h>

#define B_SZ 8
#define N_SZ 2048
#define F_SZ 128
#define ROWS_TOTAL (B_SZ * N_SZ)
#define ALPHA 0.2f
#define LN_EPS 1e-5f

// Scratch (__device__ globals: allocation-free rule)
__device__ float          g_h [ROWS_TOTAL * F_SZ];   // post-LN h fp32 (residual)
__device__ __nv_bfloat16  g_hb[ROWS_TOTAL * F_SZ];   // post-LN h bf16 (mma B operand)
__device__ float4         g_rc[ROWS_TOTAL];          // {exp(s1), exp(a*s1), -, -}
__device__ float2         g_e2[ROWS_TOTAL];          // {exp(s2), exp(a*s2)}
__device__ unsigned       g_adjbits[N_SZ * (N_SZ / 32)];

// ---------------------------------------------------------------------------
// Kernel 1: blocks [0,512): prep (scale+GEMM+LN+score factors, h fp32+bf16).
//           blocks [512,1024): pack adj -> bitmask (32 vals/thread).
// ---------------------------------------------------------------------------
__global__ void __launch_bounds__(256) prep_kernel(
    const float* __restrict__ x, const int* __restrict__ adj,
    const float* __restrict__ W, const float* __restrict__ a,
    const float* __restrict__ nw, const float* __restrict__ nb,
    const float* __restrict__ gamma, const float* __restrict__ beta)
{
    const int tid = threadIdx.x;
    if (blockIdx.x >= 512) {                               // ---- pack ----
        int gid = (blockIdx.x - 512) * 256 + tid;
        const int4* src = (const int4*)adj + (size_t)gid * 8;
        unsigned bits = 0;
#pragma unroll
        for (int u = 0; u < 8; u++) {
            int4 v = src[u];
            bits |= (v.x > 0 ? 1u : 0u) << (4 * u);
            bits |= (v.y > 0 ? 1u : 0u) << (4 * u + 1);
            bits |= (v.z > 0 ? 1u : 0u) << (4 * u + 2);
            bits |= (v.w > 0 ? 1u : 0u) << (4 * u + 3);
        }
        g_adjbits[gid] = bits;
        return;
    }

    extern __shared__ float sm[];
    float* Ws  = sm;               // 16384
    float* xs  = sm + 16384;       // 4096
    float* a1s = xs + 4096;        // 128
    float* a2s = a1s + 128;        // 128
    float* gs  = a2s + 128;        // 128
    float* bs  = gs + 128;         // 128

    const int row0 = blockIdx.x * 32;

#pragma unroll
    for (int k = 0; k < 64; k++) Ws[k * 256 + tid] = W[k * 256 + tid];
#pragma unroll
    for (int k = 0; k < 16; k++) {
        int idx = k * 256 + tid;
        int rl = idx >> 7, f = idx & 127;
        int row = row0 + rl;
        int n = row & (N_SZ - 1);
        xs[idx] = x[(size_t)row * F_SZ + f] * (1.0f + nw[n]) + nb[n];
    }
    if (tid < 128) {
        a1s[tid] = a[tid];
        a2s[tid] = a[128 + tid];
        gs[tid]  = gamma[tid];
        bs[tid]  = beta[tid];
    }
    __syncthreads();

    const int w = tid >> 5, lane = tid & 31;
    const int rbase = w * 4;
    float acc[4][4];
#pragma unroll
    for (int r = 0; r < 4; r++)
#pragma unroll
        for (int k = 0; k < 4; k++) acc[r][k] = 0.0f;

#pragma unroll 2
    for (int f = 0; f < 128; f++) {
        float w0 = Ws[f * 128 + lane];
        float w1 = Ws[f * 128 + 32 + lane];
        float w2 = Ws[f * 128 + 64 + lane];
        float w3 = Ws[f * 128 + 96 + lane];
#pragma unroll
        for (int r = 0; r < 4; r++) {
            float xv = xs[(rbase + r) * 128 + f];
            acc[r][0] += xv * w0;
            acc[r][1] += xv * w1;
            acc[r][2] += xv * w2;
            acc[r][3] += xv * w3;
        }
    }

#pragma unroll
    for (int r = 0; r < 4; r++) {
        int row = row0 + rbase + r;
        float s = acc[r][0] + acc[r][1] + acc[r][2] + acc[r][3];
#pragma unroll
        for (int o = 16; o; o >>= 1) s += __shfl_xor_sync(0xffffffffu, s, o);
        float mu = s * 0.0078125f;
        float d0 = acc[r][0] - mu, d1 = acc[r][1] - mu;
        float d2 = acc[r][2] - mu, d3 = acc[r][3] - mu;
        float v = d0 * d0 + d1 * d1 + d2 * d2 + d3 * d3;
#pragma unroll
        for (int o = 16; o; o >>= 1) v += __shfl_xor_sync(0xffffffffu, v, o);
        float rstd = rsqrtf(v * 0.0078125f + LN_EPS);
        float h0 = d0 * rstd * gs[lane]      + bs[lane];
        float h1 = d1 * rstd * gs[32 + lane] + bs[32 + lane];
        float h2 = d2 * rstd * gs[64 + lane] + bs[64 + lane];
        float h3 = d3 * rstd * gs[96 + lane] + bs[96 + lane];
        float s1p = h0 * a1s[lane] + h1 * a1s[32 + lane] + h2 * a1s[64 + lane] + h3 * a1s[96 + lane];
        float s2p = h0 * a2s[lane] + h1 * a2s[32 + lane] + h2 * a2s[64 + lane] + h3 * a2s[96 + lane];
#pragma unroll
        for (int o = 16; o; o >>= 1) {
            s1p += __shfl_xor_sync(0xffffffffu, s1p, o);
            s2p += __shfl_xor_sync(0xffffffffu, s2p, o);
        }
        size_t ro = (size_t)row * F_SZ;
        g_h[ro + lane]      = h0;
        g_h[ro + 32 + lane] = h1;
        g_h[ro + 64 + lane] = h2;
        g_h[ro + 96 + lane] = h3;
        g_hb[ro + lane]      = __float2bfloat16(h0);
        g_hb[ro + 32 + lane] = __float2bfloat16(h1);
        g_hb[ro + 64 + lane] = __float2bfloat16(h2);
        g_hb[ro + 96 + lane] = __float2bfloat16(h3);
        if (lane == 0) {
            g_rc[row] = make_float4(__expf(s1p), __expf(ALPHA * s1p), 0.0f, 0.0f);
            g_e2[row] = make_float2(__expf(s2p), __expf(ALPHA * s2p));
        }
    }
}

// ---------------------------------------------------------------------------
// Kernel 2: attention, 1024 threads (32 warps -> occ 50%), 128x128 tile.
// mma: warp w: cc=w&7 -> i-group rows cc*16 (one m16), dd=w>>3 -> f-cols dd*32.
// pass-1: warp w owns rows {w, w+32, w+64, w+96}; lane owns j=4*lane..+3;
//   p = mask ? max(E1*E2, F1*F2) : 0, ef float4 reused across the 4 rows.
// Pipeline (R10): one __syncthreads per tile; stage(T+1)+pass1(T+1) via L2
// overlap mma(T). SMEM: Hs[2][128][272B] + Ps[2][128][272B] + l_s[128].
// ---------------------------------------------------------------------------
__global__ void __launch_bounds__(1024, 1) attn_kernel(float* __restrict__ out)
{
    extern __shared__ char smc[];
    const unsigned HS_BYTES = 128 * 272;             // 34816
    const unsigned PS_OFF   = 2 * HS_BYTES;          // 69632
    const unsigned LS_OFF   = PS_OFF + 2 * HS_BYTES; // 139264

    unsigned* Ps32 = (unsigned*)(smc + PS_OFF);
    float*    l_s  = (float*)(smc + LS_OFF);         // [128]

    const unsigned smemBase = (unsigned)__cvta_generic_to_shared(smc);
    const unsigned psBase   = smemBase + PS_OFF;

    const int tid  = threadIdx.x;
    const int w    = tid >> 5;          // 0..31
    const int lane = tid & 31;
    const int cc   = w & 7;             // mma i-group
    const int dd   = w >> 3;            // mma f-block
    const int b    = blockIdx.y;
    const int i0   = blockIdx.x * 128;
    const int bN   = b * N_SZ;

    const __nv_bfloat16* hbb = g_hb + (size_t)bN * F_SZ;
    const float*         hbf = g_h  + (size_t)bN * F_SZ;

    // ---- pass-1 identity: rows w+32m, j = 4*lane..+3 ----
    float E1[4], F1[4];
#pragma unroll
    for (int m = 0; m < 4; m++) {
        float4 rc = g_rc[bN + i0 + w + 32 * m];
        E1[m] = rc.x; F1[m] = rc.y;
    }
    const unsigned* mbase0 = g_adjbits + (size_t)(i0 + w) * 64 + (lane >> 3);
    const float2*   e2b    = g_e2 + bN + 4 * lane;     // + T*128 (+2 for 2nd float4)
    const unsigned  sh0    = 4u * (unsigned)(lane & 7);

    // ---- mma ldmatrix addresses ----
    const unsigned aOff  = psBase + (unsigned)(cc * 16 + (lane & 15)) * 272
                         + (unsigned)(lane >> 4) * 16;
    const unsigned bRow  = (unsigned)(lane & 15) * 272;
    const unsigned bCol0 = (unsigned)(dd * 32 + (lane >> 4) * 8) * 2;
    const unsigned bCol1 = bCol0 + 32;

    float acc[4][4];
#pragma unroll
    for (int n = 0; n < 4; n++)
#pragma unroll
        for (int r = 0; r < 4; r++) acc[n][r] = 0.0f;
    float lacc[4] = {0.f, 0.f, 0.f, 0.f};

    // ---- staging: tile T (128x128 bf16 = 32KB) via 2 cp.async per thread ----
    auto stage = [&](int T, int buf) {
        unsigned dbase = smemBase + (unsigned)buf * HS_BYTES;
#pragma unroll
        for (int kk = 0; kk < 2; kk++) {
            int idx = kk * 1024 + tid;
            int row = idx >> 4, c16 = idx & 15;
            unsigned dst = dbase + (unsigned)row * 272 + (unsigned)c16 * 16;
            const void* src = hbb + (size_t)(T * 128 + row) * F_SZ + c16 * 8;
            asm volatile("cp.async.cg.shared.global [%0], [%1], 16;" :: "r"(dst), "l"(src));
        }
        asm volatile("cp.async.commit_group;");
    };

    // ---- pass 1 for tile T into Ps[buf] ----
    auto pass1 = [&](int T, int buf) {
        unsigned mw[4];
#pragma unroll
        for (int m = 0; m < 4; m++) mw[m] = __ldg(mbase0 + m * 32 * 64 + 4 * T);
        float4 ef0 = __ldg((const float4*)(e2b + T * 128));       // j=4l, 4l+1
        float4 ef1 = __ldg((const float4*)(e2b + T * 128 + 2));   // j=4l+2, 4l+3
        unsigned* psb = Ps32 + buf * 8704 + 2 * lane;
#pragma unroll
        for (int m = 0; m < 4; m++) {
            unsigned bits = (mw[m] >> sh0) & 0xFu;
            float pa0 = fmaxf(E1[m] * ef0.x, F1[m] * ef0.y);
            float pb0 = fmaxf(E1[m] * ef0.z, F1[m] * ef0.w);
            float pa1 = fmaxf(E1[m] * ef1.x, F1[m] * ef1.y);
            float pb1 = fmaxf(E1[m] * ef1.z, F1[m] * ef1.w);
            pa0 = (bits & 1u) ? pa0 : 0.0f;
            pb0 = (bits & 2u) ? pb0 : 0.0f;
            pa1 = (bits & 4u) ? pa1 : 0.0f;
            pb1 = (bits & 8u) ? pb1 : 0.0f;
            __nv_bfloat162 q0 = __floats2bfloat162_rn(pa0, pb0);
            __nv_bfloat162 q1 = __floats2bfloat162_rn(pa1, pb1);
            uint2 qq = make_uint2(*(unsigned*)&q0, *(unsigned*)&q1);
            *(uint2*)(psb + (w + 32 * m) * 68) = qq;
            lacc[m] += (pa0 + pb0) + (pa1 + pb1);
        }
    };

    // ---- prologue: tile 0 ----
    stage(0, 0);
    pass1(0, 0);
    asm volatile("cp.async.wait_group 0;");

    for (int T = 0; T < 16; T++) {
        const int buf = T & 1;
        __syncthreads();   // Ps[buf], Hs[buf] (tile T) visible to all warps

        if (T < 15) {
            stage(T + 1, buf ^ 1);
            pass1(T + 1, buf ^ 1);
        }

        // ---- mma(T): ACC += P[cc-group] @ H[:, dd-slab] ----
        const unsigned hsB = smemBase + (unsigned)buf * HS_BYTES;
        const unsigned psB = (unsigned)buf * HS_BYTES;
#pragma unroll
        for (int k = 0; k < 8; k++) {
            unsigned af[4];
            {
                unsigned addr = aOff + psB + (unsigned)k * 32;
                asm volatile("ldmatrix.sync.aligned.m8n8.x4.shared.b16 {%0,%1,%2,%3}, [%4];"
                             : "=r"(af[0]), "=r"(af[1]), "=r"(af[2]), "=r"(af[3])
                             : "r"(addr));
            }
            unsigned bb[2][4];
            {
                unsigned addr = hsB + bRow + (unsigned)k * 16 * 272 + bCol0;
                asm volatile("ldmatrix.sync.aligned.m8n8.x4.trans.shared.b16 {%0,%1,%2,%3}, [%4];"
                             : "=r"(bb[0][0]), "=r"(bb[0][1]), "=r"(bb[0][2]), "=r"(bb[0][3])
                             : "r"(addr));
                addr = hsB + bRow + (unsigned)k * 16 * 272 + bCol1;
                asm volatile("ldmatrix.sync.aligned.m8n8.x4.trans.shared.b16 {%0,%1,%2,%3}, [%4];"
                             : "=r"(bb[1][0]), "=r"(bb[1][1]), "=r"(bb[1][2]), "=r"(bb[1][3])
                             : "r"(addr));
            }
#pragma unroll
            for (int n = 0; n < 4; n++) {
                asm volatile(
                    "mma.sync.aligned.m16n8k16.row.col.f32.bf16.bf16.f32 "
                    "{%0,%1,%2,%3}, {%4,%5,%6,%7}, {%8,%9}, {%0,%1,%2,%3};"
                    : "+f"(acc[n][0]), "+f"(acc[n][1]),
                      "+f"(acc[n][2]), "+f"(acc[n][3])
                    : "r"(af[0]), "r"(af[1]), "r"(af[2]), "r"(af[3]),
                      "r"(bb[n >> 1][2 * (n & 1)]), "r"(bb[n >> 1][2 * (n & 1) + 1]));
            }
        }

        asm volatile("cp.async.wait_group 0;");   // own stage(T+1) copies landed
    }

    // ---- l: full warp reduce (each row owned by exactly one warp) ----
#pragma unroll
    for (int m = 0; m < 4; m++) {
#pragma unroll
        for (int o = 16; o; o >>= 1) lacc[m] += __shfl_xor_sync(0xffffffffu, lacc[m], o);
        if (lane == 0) l_s[w + 32 * m] = lacc[m];
    }
    __syncthreads();

    // ---- epilogue: normalize, +residual, elu ----
#pragma unroll
    for (int rp = 0; rp < 2; rp++) {
        int rl = cc * 16 + (lane >> 2) + 8 * rp;
        float invl = 1.0f / l_s[rl];
        int i = i0 + rl;
#pragma unroll
        for (int n = 0; n < 4; n++) {
            int col = dd * 32 + n * 8 + (lane & 3) * 2;
            const float2 r = *(const float2*)(hbf + (size_t)i * F_SZ + col);
            float ox = acc[n][2 * rp]     * invl + r.x;
            float oy = acc[n][2 * rp + 1] * invl + r.y;
            ox = ox > 0.0f ? ox : __expf(ox) - 1.0f;
            oy = oy > 0.0f ? oy : __expf(oy) - 1.0f;
            *(float2*)(out + ((size_t)bN + i) * F_SZ + col) = make_float2(ox, oy);
        }
    }
}

// ---------------------------------------------------------------------------
extern "C" void kernel_launch(void* const* d_in, const int* in_sizes, int n_in,
                              void* d_out, int out_size)
{
    const float* x     = (const float*)d_in[0];
    const int*   adj   = (const int*)d_in[1];
    const float* W     = (const float*)d_in[2];
    const float* a     = (const float*)d_in[3];
    const float* nw    = (const float*)d_in[4];
    const float* nb    = (const float*)d_in[5];
    const float* gamma = (const float*)d_in[6];
    const float* beta  = (const float*)d_in[7];
    float* out = (float*)d_out;

    const int prep_smem = (16384 + 4096 + 4 * 128) * 4;       // 83968 B
    const int attn_smem = 139264 + 512;                        // 139776 B
    cudaFuncSetAttribute(prep_kernel, cudaFuncAttributeMaxDynamicSharedMemorySize, prep_smem);
    cudaFuncSetAttribute(attn_kernel, cudaFuncAttributeMaxDynamicSharedMemorySize, attn_smem);

    prep_kernel<<<1024, 256, prep_smem>>>(x, adj, W, a, nw, nb, gamma, beta);

    dim3 grid(N_SZ / 128, B_SZ);
    attn_kernel<<<grid, 1024, attn_smem>>>(out);
}